// round 12
// baseline (speedup 1.0000x reference)
#include <cuda_runtime.h>
#include <cuda_fp16.h>
#include <cstdint>
#include <cstddef>

// Problem constants
#define NN   50000
#define EE   200000
#define RR   4
#define DIN  128
#define DH   128
#define DOUT 64
#define KK   512          // concat-K = RR * 128

#define SCAN_N (RR * NN)
#define CHUNK  2048
#define NBLK   ((SCAN_N + CHUNK - 1) / CHUNK)   // 98

// smem row stride for MMA tiles: 128 fp16 + pad = 272 bytes (bank-rotating)
#define ROWB 272

// setup kernel index ranges
#define CVT_N   (NN * DIN / 4)            // 1,600,000 float4s
#define PW1_N   (RR * 128 * 128)          // 65536
#define PW2_N   (RR * 128 * 64)           // 32768
#define SETUP_N (CVT_N + PW1_N + PW2_N)

// -------- scratch (static device globals) --------
__device__ __half g_feat16[(size_t)NN * DIN];  // feat rounded to fp16
__device__ __half g_h16[(size_t)NN * DH];      // relu(layer-1 out), fp16
__device__ __half g_w1[DH * KK];               // W1 stacked^T [128 n][512 k]
__device__ __half g_w2[DOUT * KK];             // W2 stacked^T [64 n][512 k]
__device__ int g_deg[SCAN_N];
__device__ int g_off[SCAN_N];                  // per-chunk exclusive scan
__device__ int g_cur[SCAN_N];
__device__ int g_bsum[NBLK];                   // chunk sums -> exclusive prefix
__device__ int g_done;                         // scan1 completion counter
__device__ int g_esrc[RR * EE];

__device__ __forceinline__ uint32_t smem_to_u32(const void* p) {
    uint32_t a;
    asm("{ .reg .u64 t; cvta.to.shared.u64 t, %1; cvt.u32.u64 %0, t; }"
        : "=r"(a) : "l"(p));
    return a;
}

#define LDSM_X4(r0, r1, r2, r3, addr) \
    asm volatile("ldmatrix.sync.aligned.m8n8.x4.shared.b16 {%0,%1,%2,%3}, [%4];" \
                 : "=r"(r0), "=r"(r1), "=r"(r2), "=r"(r3) : "r"(addr))

#define MMA_F16(c, a, b0, b1) \
    asm volatile("mma.sync.aligned.m16n8k16.row.col.f32.f16.f16.f32 " \
                 "{%0,%1,%2,%3},{%4,%5,%6,%7},{%8,%9},{%0,%1,%2,%3};" \
                 : "+f"((c)[0]), "+f"((c)[1]), "+f"((c)[2]), "+f"((c)[3]) \
                 : "r"((a)[0]), "r"((a)[1]), "r"((a)[2]), "r"((a)[3]), \
                   "r"(b0), "r"(b1))

// ==================== fused setup: zero + cvt feat + prep W1/W2 =============
__global__ void k_setup(const float* __restrict__ feat,
                        const float* __restrict__ W1,
                        const float* __restrict__ W2) {
    const int i = blockIdx.x * 256 + threadIdx.x;
    if (i == 0) g_done = 0;
    if (i < SCAN_N) { g_deg[i] = 0; g_cur[i] = 0; }
    if (i < CVT_N) {
        float4 v = reinterpret_cast<const float4*>(feat)[i];
        reinterpret_cast<__half2*>(g_feat16)[2 * i]     = __floats2half2_rn(v.x, v.y);
        reinterpret_cast<__half2*>(g_feat16)[2 * i + 1] = __floats2half2_rn(v.z, v.w);
    } else if (i < CVT_N + PW1_N) {
        const int j = i - CVT_N;                 // W1 [r][k=128][n=128]
        const int r = j >> 14, k = (j >> 7) & 127, n = j & 127;
        g_w1[n * KK + r * 128 + k] = __float2half(W1[j]);
    } else if (i < SETUP_N) {
        const int j = i - CVT_N - PW1_N;         // W2 [r][k=128][n=64]
        const int r = j / 8192, k = (j >> 6) & 127, n = j & 63;
        g_w2[n * KK + r * 128 + k] = __float2half(W2[j]);
    }
}

// ==================== degree / CSR build ====================
__global__ void k_count(const int* __restrict__ edges) {
    int i = blockIdx.x * 256 + threadIdx.x;
    if (i >= RR * EE) return;
    int r = i / EE, e = i - r * EE;
    int dst = edges[r * 2 * EE + EE + e];
    atomicAdd(&g_deg[r * NN + dst], 1);
}

// per-chunk scan; LAST block to finish also exclusive-scans the chunk sums
__global__ __launch_bounds__(256) void k_scan1() {
    __shared__ int wsum[8];
    __shared__ int ws2[4];
    __shared__ int sLast;
    const int b = blockIdx.x, t = threadIdx.x;
    const int base = b * CHUNK + t * 8;
    int v[8]; int s = 0;
#pragma unroll
    for (int i = 0; i < 8; ++i) {
        int idx = base + i;
        int x = (idx < SCAN_N) ? g_deg[idx] : 0;
        v[i] = s; s += x;
    }
    const int lane = t & 31, w = t >> 5;
    int x = s;
#pragma unroll
    for (int o = 1; o < 32; o <<= 1) {
        int n = __shfl_up_sync(~0u, x, o);
        if (lane >= o) x += n;
    }
    if (lane == 31) wsum[w] = x;
    __syncthreads();
    if (t == 0) {
        int acc = 0;
#pragma unroll
        for (int i = 0; i < 8; ++i) { int tmp = wsum[i]; wsum[i] = acc; acc += tmp; }
        g_bsum[b] = acc;
    }
    __syncthreads();
    const int toff = wsum[w] + (x - s);
#pragma unroll
    for (int i = 0; i < 8; ++i) {
        int idx = base + i;
        if (idx < SCAN_N) g_off[idx] = toff + v[i];
    }
    // fused cross-chunk scan: last-arriving block does it
    if (t == 0) {
        __threadfence();
        sLast = (atomicAdd(&g_done, 1) == NBLK - 1) ? 1 : 0;
    }
    __syncthreads();
    if (!sLast) return;
    __threadfence();
    int bv = 0;
    if (t < NBLK) bv = g_bsum[t];
    int bx = bv;
    if (w < 4) {
#pragma unroll
        for (int o = 1; o < 32; o <<= 1) {
            int n = __shfl_up_sync(~0u, bx, o);
            if (lane >= o) bx += n;
        }
        if (lane == 31) ws2[w] = bx;
    }
    __syncthreads();
    if (t == 0) {
        int acc = 0;
#pragma unroll
        for (int i = 0; i < 4; ++i) { int tmp = ws2[i]; ws2[i] = acc; acc += tmp; }
    }
    __syncthreads();
    if (t < NBLK) g_bsum[t] = (bx - bv) + ws2[w];
}

// bin with chunk-offset folded in
__global__ void k_bin(const int* __restrict__ edges) {
    int i = blockIdx.x * 256 + threadIdx.x;
    if (i >= RR * EE) return;
    int r = i / EE, e = i - r * EE;
    const int* eb = edges + r * 2 * EE;
    int src = eb[e];
    int dst = eb[EE + e];
    int idx = r * NN + dst;
    int pos = g_off[idx] + g_bsum[idx >> 11] + atomicAdd(&g_cur[idx], 1);
    g_esrc[pos] = src;
}

// ==================== fused gather + fp16 GEMM, K=512 =======================
// C = [mean-gather(F) per etype, concat-K] @ B^T (+gated bias)(+relu).
// K-chunk kc == etype kc: gather etype-kc means for the CTA's 128 nodes
// DIRECTLY into the smem A tile (no global Z buffer).
// CTA: 256 thr = 8 warps, tile 128m x NB n. Warp grid 2m x 4n in mainloop;
// in gather phase each warp owns 16 consecutive nodes.
template <int ROWS>
__device__ __forceinline__ void load_tileB(char* dst, const __half* __restrict__ src,
                                           int tid) {
#pragma unroll
    for (int i = 0; i < ROWS * 16 / 256; ++i) {
        const int j = i * 256 + tid;
        const int row = j >> 4;
        const int c16 = j & 15;
        uint4 v = *reinterpret_cast<const uint4*>(src + (size_t)row * KK + c16 * 8);
        *reinterpret_cast<uint4*>(dst + row * ROWB + c16 * 16) = v;
    }
}

template <int NB, bool RELU, bool HALF_OUT>
__global__ __launch_bounds__(256, 2)
void k_mma_fused(const __half* __restrict__ F,   // [N][128] fp16 node features
                 const __half* __restrict__ B,   // [NB][512]
                 const float* __restrict__ bias, // [RR][NB]
                 void* __restrict__ Cv)          // [N][NB] fp16 or fp32
{
    constexpr int NT = NB / 64;
    extern __shared__ __align__(16) char smem[];
    char* sA = smem;                                    // 128 x ROWB
    char* sB = sA + 128 * ROWB;                         // NB x ROWB
    float* bs = reinterpret_cast<float*>(sB + NB * ROWB);      // [RR*NB]
    unsigned char* sGate = reinterpret_cast<unsigned char*>(bs + RR * NB); // [128]

    const int tid  = threadIdx.x;
    const int lane = tid & 31;
    const int wid  = tid >> 5;
    const int m0   = blockIdx.x * 128;

#pragma unroll
    for (int i = tid; i < RR * NB; i += 256) bs[i] = bias[i];
    if (tid < 128) sGate[tid] = 0;

    const int wm = (wid >> 2) * 64;
    const int wn = (wid & 3) * (NB / 4);
    const int aoff = (lane & 15) * ROWB + (lane >> 4) * 16;
    const int boff = ((lane & 7) + ((lane >> 4) << 3)) * ROWB + ((lane >> 3) & 1) * 16;

    const uint32_t uA = smem_to_u32(sA);
    const uint32_t uB = smem_to_u32(sB);

    float acc[4][NT * 2][4];
#pragma unroll
    for (int mt = 0; mt < 4; ++mt)
#pragma unroll
        for (int nt = 0; nt < NT * 2; ++nt)
#pragma unroll
            for (int q = 0; q < 4; ++q) acc[mt][nt][q] = 0.f;

    for (int kc = 0; kc < RR; ++kc) {   // chunk == etype
        if (kc) __syncthreads();
        // gather-mean etype kc into sA: warp owns nodes wid*16 .. wid*16+15
#pragma unroll 1
        for (int i = 0; i < 16; ++i) {
            const int ln = wid * 16 + i;
            const int node = m0 + ln;
            float4 s = make_float4(0.f, 0.f, 0.f, 0.f);
            int deg = 0;
            if (node < NN) {
                const int idx = kc * NN + node;
                deg = g_deg[idx];
                if (deg > 0) {
                    const int beg = g_off[idx] + g_bsum[idx >> 11];
                    for (int bse = 0; bse < deg; bse += 32) {
                        const int my = bse + lane;
                        const int src_l = (my < deg) ? g_esrc[beg + my] : 0;
                        const int n = min(32, deg - bse);
                        for (int j = 0; j < n; ++j) {
                            const int src = __shfl_sync(~0u, src_l, j);
                            const uint2 u = *reinterpret_cast<const uint2*>(
                                F + (size_t)src * 128 + lane * 4);
                            const float2 f0 =
                                __half22float2(*reinterpret_cast<const __half2*>(&u.x));
                            const float2 f1 =
                                __half22float2(*reinterpret_cast<const __half2*>(&u.y));
                            s.x += f0.x; s.y += f0.y; s.z += f1.x; s.w += f1.y;
                        }
                    }
                    const float d = 1.0f / (float)deg;
                    s.x *= d; s.y *= d; s.z *= d; s.w *= d;
                }
            }
            __half2 p0 = __floats2half2_rn(s.x, s.y);
            __half2 p1 = __floats2half2_rn(s.z, s.w);
            uint2 wv;
            wv.x = *reinterpret_cast<uint32_t*>(&p0);
            wv.y = *reinterpret_cast<uint32_t*>(&p1);
            *reinterpret_cast<uint2*>(sA + ln * ROWB + lane * 8) = wv;
            if (lane == 0 && deg > 0) sGate[ln] |= (unsigned char)(1u << kc);
        }
        // B chunk
        load_tileB<NB>(sB, B + kc * 128, tid);
        __syncthreads();

#pragma unroll
        for (int ks = 0; ks < 8; ++ks) {
            const int kb = ks * 32;
            uint32_t a[4][4];
#pragma unroll
            for (int mt = 0; mt < 4; ++mt) {
                const uint32_t base = (wm + mt * 16) * ROWB + aoff + kb;
                LDSM_X4(a[mt][0], a[mt][1], a[mt][2], a[mt][3], uA + base);
            }
#pragma unroll
            for (int jt = 0; jt < NT; ++jt) {
                const uint32_t bbase = (wn + jt * 16) * ROWB + boff + kb;
                uint32_t b[4];
                LDSM_X4(b[0], b[1], b[2], b[3], uB + bbase);
#pragma unroll
                for (int mt = 0; mt < 4; ++mt) {
                    MMA_F16(acc[mt][2 * jt],     a[mt], b[0], b[1]);
                    MMA_F16(acc[mt][2 * jt + 1], a[mt], b[2], b[3]);
                }
            }
        }
    }

    // fused epilogue: + gated bias, optional relu, store fp16 or fp32
#pragma unroll
    for (int mt = 0; mt < 4; ++mt) {
        const int rbase = m0 + wm + mt * 16 + (lane >> 2);
#pragma unroll
        for (int half = 0; half < 2; ++half) {
            const int row = rbase + half * 8;
            if (row >= NN) continue;
            const unsigned g = sGate[row - m0];
#pragma unroll
            for (int nt = 0; nt < NT * 2; ++nt) {
                const int col = wn + nt * 8 + (lane & 3) * 2;
                float bx = 0.f, by = 0.f;
#pragma unroll
                for (int r = 0; r < RR; ++r) {
                    if ((g >> r) & 1) {
                        bx += bs[r * NB + col];
                        by += bs[r * NB + col + 1];
                    }
                }
                float x = acc[mt][nt][half * 2 + 0] + bx;
                float y = acc[mt][nt][half * 2 + 1] + by;
                if (RELU) { x = fmaxf(x, 0.f); y = fmaxf(y, 0.f); }
                if (HALF_OUT) {
                    *reinterpret_cast<__half2*>(
                        reinterpret_cast<__half*>(Cv) + (size_t)row * NB + col) =
                        __floats2half2_rn(x, y);
                } else {
                    *reinterpret_cast<float2*>(
                        reinterpret_cast<float*>(Cv) + (size_t)row * NB + col) =
                        make_float2(x, y);
                }
            }
        }
    }
}

// ==================== launch ====================
extern "C" void kernel_launch(void* const* d_in, const int* in_sizes, int n_in,
                              void* d_out, int out_size) {
    const float* feat  = (const float*)d_in[0];
    const float* W1    = (const float*)d_in[1];
    const float* b1    = (const float*)d_in[2];
    const float* W2    = (const float*)d_in[3];
    const float* b2    = (const float*)d_in[4];
    const int*   edges = (const int*)d_in[5];
    float* out = (float*)d_out;

    void *pF16, *pH16, *pW1, *pW2;
    cudaGetSymbolAddress(&pF16, g_feat16);
    cudaGetSymbolAddress(&pH16, g_h16);
    cudaGetSymbolAddress(&pW1,  g_w1);
    cudaGetSymbolAddress(&pW2,  g_w2);

    const int smem1 = (128 + 128) * ROWB + RR * 128 * 4 + 128;  // 71936
    const int smem2 = (128 + 64) * ROWB + RR * 64 * 4 + 128;    // 53376
    cudaFuncSetAttribute((const void*)k_mma_fused<128, true, true>,
                         cudaFuncAttributeMaxDynamicSharedMemorySize, smem1);
    cudaFuncSetAttribute((const void*)k_mma_fused<64, false, false>,
                         cudaFuncAttributeMaxDynamicSharedMemorySize, smem2);

    const dim3 gg((NN + 127) / 128);

    // 1: fused setup (reset g_done, zero counters, cvt feat, prep W1/W2)
    k_setup<<<(SETUP_N + 255) / 256, 256>>>(feat, W1, W2);
    // 2-4: CSR build (scan2 fused into scan1's last block)
    k_count<<<(RR * EE + 255) / 256, 256>>>(edges);
    k_scan1<<<NBLK, 256>>>();
    k_bin<<<(RR * EE + 255) / 256, 256>>>(edges);

    // 5: layer 1 — fused gather+GEMM, bias+relu epilogue -> h16
    k_mma_fused<128, true, true><<<gg, 256, smem1>>>(
        (const __half*)pF16, (const __half*)pW1, b1, pH16);

    // 6: layer 2 — fused gather+GEMM, writes fp32 out
    k_mma_fused<64, false, false><<<gg, 256, smem2>>>(
        (const __half*)pH16, (const __half*)pW2, b2, out);
}

// round 13
// speedup vs baseline: 2.0778x; 2.0778x over previous
#include <cuda_runtime.h>
#include <cuda_fp16.h>
#include <cstdint>
#include <cstddef>

// Problem constants
#define NN   50000
#define EE   200000
#define RR   4
#define DIN  128
#define DH   128
#define DOUT 64
#define KK   512          // concat-K = RR * 128

#define SCAN_N (RR * NN)
#define CHUNK  2048
#define NBLK   ((SCAN_N + CHUNK - 1) / CHUNK)   // 98

// smem row stride for MMA tiles: 128 fp16 + pad = 272 bytes (bank-rotating)
#define ROWB 272

// setup kernel index ranges
#define CVT_N   (NN * DIN / 4)            // 1,600,000 float4s
#define PW1_N   (RR * 128 * 128)          // 65536
#define PW2_N   (RR * 128 * 64)           // 32768
#define SETUP_N (CVT_N + PW1_N + PW2_N)

// -------- scratch (static device globals) --------
__device__ __half g_Z[(size_t)NN * KK];        // agg means, fp16  [N][512]
__device__ __half g_feat16[(size_t)NN * DIN];  // feat rounded to fp16
__device__ __half g_h16[(size_t)NN * DH];      // relu(layer-1 out), fp16
__device__ __half g_w1[DH * KK];               // W1 stacked^T [128 n][512 k]
__device__ __half g_w2[DOUT * KK];             // W2 stacked^T [64 n][512 k]
__device__ unsigned char g_gate[NN];           // per-node etype gate bits
__device__ int g_deg[SCAN_N];
__device__ int g_off[SCAN_N];                  // per-chunk exclusive scan
__device__ int g_cur[SCAN_N];
__device__ int g_bsum[NBLK];                   // chunk sums -> exclusive prefix
__device__ int g_done;                         // scan1 completion counter
__device__ int g_esrc[RR * EE];

__device__ __forceinline__ uint32_t smem_to_u32(const void* p) {
    uint32_t a;
    asm("{ .reg .u64 t; cvta.to.shared.u64 t, %1; cvt.u32.u64 %0, t; }"
        : "=r"(a) : "l"(p));
    return a;
}

#define LDSM_X4(r0, r1, r2, r3, addr) \
    asm volatile("ldmatrix.sync.aligned.m8n8.x4.shared.b16 {%0,%1,%2,%3}, [%4];" \
                 : "=r"(r0), "=r"(r1), "=r"(r2), "=r"(r3) : "r"(addr))

#define MMA_F16(c, a, b0, b1) \
    asm volatile("mma.sync.aligned.m16n8k16.row.col.f32.f16.f16.f32 " \
                 "{%0,%1,%2,%3},{%4,%5,%6,%7},{%8,%9},{%0,%1,%2,%3};" \
                 : "+f"((c)[0]), "+f"((c)[1]), "+f"((c)[2]), "+f"((c)[3]) \
                 : "r"((a)[0]), "r"((a)[1]), "r"((a)[2]), "r"((a)[3]), \
                   "r"(b0), "r"(b1))

// ==================== fused setup: zero + cvt feat + prep W1/W2 =============
__global__ void k_setup(const float* __restrict__ feat,
                        const float* __restrict__ W1,
                        const float* __restrict__ W2) {
    const int i = blockIdx.x * 256 + threadIdx.x;
    if (i == 0) g_done = 0;
    if (i < SCAN_N) { g_deg[i] = 0; g_cur[i] = 0; }
    if (i < CVT_N) {
        float4 v = reinterpret_cast<const float4*>(feat)[i];
        reinterpret_cast<__half2*>(g_feat16)[2 * i]     = __floats2half2_rn(v.x, v.y);
        reinterpret_cast<__half2*>(g_feat16)[2 * i + 1] = __floats2half2_rn(v.z, v.w);
    } else if (i < CVT_N + PW1_N) {
        const int j = i - CVT_N;                 // W1 [r][k=128][n=128]
        const int r = j >> 14, k = (j >> 7) & 127, n = j & 127;
        g_w1[n * KK + r * 128 + k] = __float2half(W1[j]);
    } else if (i < SETUP_N) {
        const int j = i - CVT_N - PW1_N;         // W2 [r][k=128][n=64]
        const int r = j / 8192, k = (j >> 6) & 127, n = j & 63;
        g_w2[n * KK + r * 128 + k] = __float2half(W2[j]);
    }
}

// ==================== degree / CSR build ====================
__global__ void k_count(const int* __restrict__ edges) {
    int i = blockIdx.x * 256 + threadIdx.x;
    if (i >= RR * EE) return;
    int r = i / EE, e = i - r * EE;
    int dst = edges[r * 2 * EE + EE + e];
    atomicAdd(&g_deg[r * NN + dst], 1);
}

// per-chunk scan; LAST block to finish also exclusive-scans the chunk sums
__global__ __launch_bounds__(256) void k_scan1() {
    __shared__ int wsum[8];
    __shared__ int ws2[4];
    __shared__ int sLast;
    const int b = blockIdx.x, t = threadIdx.x;
    const int base = b * CHUNK + t * 8;
    int v[8]; int s = 0;
#pragma unroll
    for (int i = 0; i < 8; ++i) {
        int idx = base + i;
        int x = (idx < SCAN_N) ? g_deg[idx] : 0;
        v[i] = s; s += x;
    }
    const int lane = t & 31, w = t >> 5;
    int x = s;
#pragma unroll
    for (int o = 1; o < 32; o <<= 1) {
        int n = __shfl_up_sync(~0u, x, o);
        if (lane >= o) x += n;
    }
    if (lane == 31) wsum[w] = x;
    __syncthreads();
    if (t == 0) {
        int acc = 0;
#pragma unroll
        for (int i = 0; i < 8; ++i) { int tmp = wsum[i]; wsum[i] = acc; acc += tmp; }
        g_bsum[b] = acc;
    }
    __syncthreads();
    const int toff = wsum[w] + (x - s);
#pragma unroll
    for (int i = 0; i < 8; ++i) {
        int idx = base + i;
        if (idx < SCAN_N) g_off[idx] = toff + v[i];
    }
    // fused cross-chunk scan: last-arriving block does it
    if (t == 0) {
        __threadfence();
        sLast = (atomicAdd(&g_done, 1) == NBLK - 1) ? 1 : 0;
    }
    __syncthreads();
    if (!sLast) return;
    __threadfence();
    int bv = 0;
    if (t < NBLK) bv = g_bsum[t];
    int bx = bv;
    if (w < 4) {
#pragma unroll
        for (int o = 1; o < 32; o <<= 1) {
            int n = __shfl_up_sync(~0u, bx, o);
            if (lane >= o) bx += n;
        }
        if (lane == 31) ws2[w] = bx;
    }
    __syncthreads();
    if (t == 0) {
        int acc = 0;
#pragma unroll
        for (int i = 0; i < 4; ++i) { int tmp = ws2[i]; ws2[i] = acc; acc += tmp; }
    }
    __syncthreads();
    if (t < NBLK) g_bsum[t] = (bx - bv) + ws2[w];
}

// bin with chunk-offset folded in
__global__ void k_bin(const int* __restrict__ edges) {
    int i = blockIdx.x * 256 + threadIdx.x;
    if (i >= RR * EE) return;
    int r = i / EE, e = i - r * EE;
    const int* eb = edges + r * 2 * EE;
    int src = eb[e];
    int dst = eb[EE + e];
    int idx = r * NN + dst;
    int pos = g_off[idx] + g_bsum[idx >> 11] + atomicAdd(&g_cur[idx], 1);
    g_esrc[pos] = src;
}

// ==================== aggregate-first gather (mean of fp16 F rows) ==========
__global__ __launch_bounds__(256)
void k_aggZ(const __half* __restrict__ F, __half* __restrict__ Z) {
    const int gw = (blockIdx.x * 256 + threadIdx.x) >> 5;
    if (gw >= NN) return;
    const int lane = threadIdx.x & 31;
    unsigned mask = 0;
#pragma unroll
    for (int r = 0; r < RR; ++r) {
        const int idx = r * NN + gw;
        const int deg = g_deg[idx];
        float4 s = make_float4(0.f, 0.f, 0.f, 0.f);
        if (deg > 0) {
            mask |= 1u << r;
            const int beg = g_off[idx] + g_bsum[idx >> 11];
            for (int bse = 0; bse < deg; bse += 32) {
                const int my = bse + lane;
                const int src_l = (my < deg) ? g_esrc[beg + my] : 0;
                const int n = min(32, deg - bse);
                for (int j = 0; j < n; ++j) {
                    const int src = __shfl_sync(~0u, src_l, j);
                    const uint2 u = *reinterpret_cast<const uint2*>(
                        F + (size_t)src * 128 + lane * 4);
                    const float2 f0 = __half22float2(*reinterpret_cast<const __half2*>(&u.x));
                    const float2 f1 = __half22float2(*reinterpret_cast<const __half2*>(&u.y));
                    s.x += f0.x; s.y += f0.y; s.z += f1.x; s.w += f1.y;
                }
            }
            const float d = 1.0f / (float)deg;
            s.x *= d; s.y *= d; s.z *= d; s.w *= d;
        }
        const size_t o2 = ((size_t)gw * KK + r * 128 + lane * 4) >> 1;  // half2 idx
        reinterpret_cast<__half2*>(Z)[o2]     = __floats2half2_rn(s.x, s.y);
        reinterpret_cast<__half2*>(Z)[o2 + 1] = __floats2half2_rn(s.z, s.w);
    }
    if (lane == 0) g_gate[gw] = (unsigned char)mask;
}

// ==================== fp16 GEMM (single pass), K=512, fused epilogue ========
// C = A @ B^T (+ gated bias) (+relu). A [N][512] fp16; B [NB][512] fp16.
// CTA: 256 thr = 8 warps, tile 128m x NB n; K streamed in 4 chunks of 128.
// Warp grid 2m x 4n: warp = 64m x NB/4 n; mt=4 m16 tiles; NT = NB/64 jt-steps.
template <int ROWS>
__device__ __forceinline__ void load_tile512(char* dst, const __half* __restrict__ src,
                                             int valid_rows, int tid) {
#pragma unroll
    for (int i = 0; i < ROWS * 16 / 256; ++i) {
        const int j = i * 256 + tid;
        const int row = j >> 4;
        const int c16 = j & 15;
        uint4 v = make_uint4(0u, 0u, 0u, 0u);
        if (row < valid_rows)
            v = *reinterpret_cast<const uint4*>(src + (size_t)row * KK + c16 * 8);
        *reinterpret_cast<uint4*>(dst + row * ROWB + c16 * 16) = v;
    }
}

template <int NB, bool RELU, bool HALF_OUT>
__global__ __launch_bounds__(256, 2)
void k_mma(const __half* __restrict__ A, const __half* __restrict__ B,
           const float* __restrict__ bias,      // [RR][NB]
           void* __restrict__ Cv)               // [N][NB] fp16 or fp32
{
    constexpr int NT = NB / 64;
    extern __shared__ __align__(16) char smem[];
    char* sA = smem;
    char* sB = sA + 128 * ROWB;
    float* bs = reinterpret_cast<float*>(sB + NB * ROWB);  // [RR*NB]

    const int tid  = threadIdx.x;
    const int lane = tid & 31;
    const int wid  = tid >> 5;
    const int m0   = blockIdx.x * 128;
    const int validA = (NN - m0) < 128 ? (NN - m0) : 128;

#pragma unroll
    for (int i = tid; i < RR * NB; i += 256) bs[i] = bias[i];

    const int wm = (wid >> 2) * 64;
    const int wn = (wid & 3) * (NB / 4);
    const int aoff = (lane & 15) * ROWB + (lane >> 4) * 16;
    const int boff = ((lane & 7) + ((lane >> 4) << 3)) * ROWB + ((lane >> 3) & 1) * 16;

    const uint32_t uA = smem_to_u32(sA);
    const uint32_t uB = smem_to_u32(sB);

    float acc[4][NT * 2][4];
#pragma unroll
    for (int mt = 0; mt < 4; ++mt)
#pragma unroll
        for (int nt = 0; nt < NT * 2; ++nt)
#pragma unroll
            for (int q = 0; q < 4; ++q) acc[mt][nt][q] = 0.f;

    for (int kc = 0; kc < 4; ++kc) {
        if (kc) __syncthreads();
        load_tile512<128>(sA, A + (size_t)m0 * KK + kc * 128, validA, tid);
        load_tile512<NB>(sB, B + kc * 128, NB, tid);
        __syncthreads();

#pragma unroll
        for (int ks = 0; ks < 8; ++ks) {
            const int kb = ks * 32;
            uint32_t a[4][4];
#pragma unroll
            for (int mt = 0; mt < 4; ++mt) {
                const uint32_t base = (wm + mt * 16) * ROWB + aoff + kb;
                LDSM_X4(a[mt][0], a[mt][1], a[mt][2], a[mt][3], uA + base);
            }
#pragma unroll
            for (int jt = 0; jt < NT; ++jt) {
                const uint32_t bbase = (wn + jt * 16) * ROWB + boff + kb;
                uint32_t b[4];
                LDSM_X4(b[0], b[1], b[2], b[3], uB + bbase);
#pragma unroll
                for (int mt = 0; mt < 4; ++mt) {
                    MMA_F16(acc[mt][2 * jt],     a[mt], b[0], b[1]);
                    MMA_F16(acc[mt][2 * jt + 1], a[mt], b[2], b[3]);
                }
            }
        }
    }

    // fused epilogue: + gated bias, optional relu, store fp16 or fp32
#pragma unroll
    for (int mt = 0; mt < 4; ++mt) {
        const int rbase = m0 + wm + mt * 16 + (lane >> 2);
#pragma unroll
        for (int half = 0; half < 2; ++half) {
            const int row = rbase + half * 8;
            if (row >= NN) continue;
            const unsigned g = g_gate[row];
#pragma unroll
            for (int nt = 0; nt < NT * 2; ++nt) {
                const int col = wn + nt * 8 + (lane & 3) * 2;
                float bx = 0.f, by = 0.f;
#pragma unroll
                for (int r = 0; r < RR; ++r) {
                    if ((g >> r) & 1) {
                        bx += bs[r * NB + col];
                        by += bs[r * NB + col + 1];
                    }
                }
                float x = acc[mt][nt][half * 2 + 0] + bx;
                float y = acc[mt][nt][half * 2 + 1] + by;
                if (RELU) { x = fmaxf(x, 0.f); y = fmaxf(y, 0.f); }
                if (HALF_OUT) {
                    *reinterpret_cast<__half2*>(
                        reinterpret_cast<__half*>(Cv) + (size_t)row * NB + col) =
                        __floats2half2_rn(x, y);
                } else {
                    *reinterpret_cast<float2*>(
                        reinterpret_cast<float*>(Cv) + (size_t)row * NB + col) =
                        make_float2(x, y);
                }
            }
        }
    }
}

// ==================== launch ====================
extern "C" void kernel_launch(void* const* d_in, const int* in_sizes, int n_in,
                              void* d_out, int out_size) {
    const float* feat  = (const float*)d_in[0];
    const float* W1    = (const float*)d_in[1];
    const float* b1    = (const float*)d_in[2];
    const float* W2    = (const float*)d_in[3];
    const float* b2    = (const float*)d_in[4];
    const int*   edges = (const int*)d_in[5];
    float* out = (float*)d_out;

    void *pZ, *pF16, *pH16, *pW1, *pW2;
    cudaGetSymbolAddress(&pZ,   g_Z);
    cudaGetSymbolAddress(&pF16, g_feat16);
    cudaGetSymbolAddress(&pH16, g_h16);
    cudaGetSymbolAddress(&pW1,  g_w1);
    cudaGetSymbolAddress(&pW2,  g_w2);

    const int smem1 = (128 + 128) * ROWB + RR * 128 * 4;  // 71680
    const int smem2 = (128 + 64) * ROWB + RR * 64 * 4;    // 53248
    cudaFuncSetAttribute((const void*)k_mma<128, true, true>,
                         cudaFuncAttributeMaxDynamicSharedMemorySize, smem1);
    cudaFuncSetAttribute((const void*)k_mma<64, false, false>,
                         cudaFuncAttributeMaxDynamicSharedMemorySize, smem2);

    const dim3 gg((NN + 127) / 128);
    const int aggGrid = (NN * 32 + 255) / 256;

    // 1: fused setup (reset g_done, zero counters, cvt feat, prep W1/W2)
    k_setup<<<(SETUP_N + 255) / 256, 256>>>(feat, W1, W2);
    // 2-4: CSR build (cross-chunk scan fused into scan1's last block)
    k_count<<<(RR * EE + 255) / 256, 256>>>(edges);
    k_scan1<<<NBLK, 256>>>();
    k_bin<<<(RR * EE + 255) / 256, 256>>>(edges);

    // 5-6: layer 1
    k_aggZ<<<aggGrid, 256>>>((const __half*)pF16, (__half*)pZ);
    k_mma<128, true, true><<<gg, 256, smem1>>>(
        (const __half*)pZ, (const __half*)pW1, b1, pH16);

    // 7-8: layer 2
    k_aggZ<<<aggGrid, 256>>>((const __half*)pH16, (__half*)pZ);
    k_mma<64, false, false><<<gg, 256, smem2>>>(
        (const __half*)pZ, (const __half*)pW2, b2, out);
}